// round 11
// baseline (speedup 1.0000x reference)
#include <cuda_runtime.h>
#include <cuda_bf16.h>
#include <cstdint>
#include <math.h>

#define CC    64
#define NN    9216
#define BBATCH 2
#define BNTOK 18432      // BBATCH * NN
#define HID   256
#define BK    128
#define SCALE 0.125f     // C^-0.5

// ---------------- scratch (device globals: no allocations allowed) ----------
__device__ float g_h  [BNTOK*CC];   // LN1 output
__device__ float g_att[BNTOK*CC];   // attention output (valid rows only)
__device__ __nv_bfloat16 g_qh[BNTOK*CC];   // pre-scaled by 0.125
__device__ __nv_bfloat16 g_kh[BNTOK*CC];
__device__ __nv_bfloat16 g_vh[BNTOK*CC];
__device__ int g_cidx[BNTOK];       // compacted -> original token (per batch)
__device__ int g_nv[BBATCH];        // valid count per batch

// ---------------- helpers ----------------------------------------------------
__device__ __forceinline__ void ldsm_x4(uint32_t& r0, uint32_t& r1, uint32_t& r2,
                                        uint32_t& r3, uint32_t addr) {
    asm volatile("ldmatrix.sync.aligned.m8n8.x4.shared.b16 {%0,%1,%2,%3}, [%4];"
                 : "=r"(r0), "=r"(r1), "=r"(r2), "=r"(r3) : "r"(addr));
}
__device__ __forceinline__ void ldsm_x4_t(uint32_t& r0, uint32_t& r1, uint32_t& r2,
                                          uint32_t& r3, uint32_t addr) {
    asm volatile("ldmatrix.sync.aligned.m8n8.x4.trans.shared.b16 {%0,%1,%2,%3}, [%4];"
                 : "=r"(r0), "=r"(r1), "=r"(r2), "=r"(r3) : "r"(addr));
}
__device__ __forceinline__ void mma_bf16(float* c, const uint32_t* a,
                                         uint32_t b0, uint32_t b1) {
    asm volatile("mma.sync.aligned.m16n8k16.row.col.f32.bf16.bf16.f32 "
                 "{%0,%1,%2,%3}, {%4,%5,%6,%7}, {%8,%9}, {%0,%1,%2,%3};"
                 : "+f"(c[0]), "+f"(c[1]), "+f"(c[2]), "+f"(c[3])
                 : "r"(a[0]), "r"(a[1]), "r"(a[2]), "r"(a[3]), "r"(b0), "r"(b1));
}
__device__ __forceinline__ void cpa16(uint32_t saddr, const void* g) {
    asm volatile("cp.async.cg.shared.global [%0], [%1], 16;" :: "r"(saddr), "l"(g));
}
__device__ __forceinline__ void cpa_commit() {
    asm volatile("cp.async.commit_group;");
}
template <int N>
__device__ __forceinline__ void cpa_wait() {
    asm volatile("cp.async.wait_group %0;" :: "n"(N));
}
__device__ __forceinline__ uint64_t pk2(float x, float y) {
    uint64_t r; asm("mov.b64 %0, {%1,%2};" : "=l"(r) : "f"(x), "f"(y)); return r;
}
__device__ __forceinline__ void upk2(float& x, float& y, uint64_t p) {
    asm("mov.b64 {%0,%1}, %2;" : "=f"(x), "=f"(y) : "l"(p));
}
__device__ __forceinline__ uint64_t fma2(uint64_t a, uint64_t b, uint64_t c) {
    uint64_t d; asm("fma.rn.f32x2 %0,%1,%2,%3;" : "=l"(d) : "l"(a), "l"(b), "l"(c));
    return d;
}
__device__ __forceinline__ uint64_t mul2(uint64_t a, uint64_t b) {
    uint64_t d; asm("mul.rn.f32x2 %0,%1,%2;" : "=l"(d) : "l"(a), "l"(b)); return d;
}
__device__ __forceinline__ uint64_t add2(uint64_t a, uint64_t b) {
    uint64_t d; asm("add.rn.f32x2 %0,%1,%2;" : "=l"(d) : "l"(a), "l"(b)); return d;
}
__device__ __forceinline__ uint32_t cvtbf2(float x, float y) {
    uint32_t d; asm("cvt.rn.bf16x2.f32 %0, %1, %2;" : "=r"(d) : "f"(y), "f"(x));
    return d;
}
#define SWZ(off) ((off) ^ (((off) >> 3) & 0x70))

// ---------------- fp32 tile loader ------------------------------------------
__device__ __forceinline__ void load_tile64(const float* __restrict__ gptr,
                                            float* __restrict__ s, int tid) {
#pragma unroll
    for (int it = 0; it < 4; ++it) {
        int l = tid + it * 256;
        float4 val = ((const float4*)gptr)[l];
        int r = l >> 4;
        int c = (l & 15) * 4;
        float* d = s + r * 65 + c;
        d[0] = val.x; d[1] = val.y; d[2] = val.z; d[3] = val.w;
    }
}
// gathered variant: row r comes from rows[r] (token index within full array)
__device__ __forceinline__ void load_tile64_g(const float* __restrict__ base,
                                              const int* __restrict__ rows,
                                              float* __restrict__ s, int tid) {
#pragma unroll
    for (int it = 0; it < 4; ++it) {
        int l = tid + it * 256;
        int r = l >> 4;
        int c = (l & 15) * 4;
        float4 val = *(const float4*)(base + (size_t)rows[r] * CC + c);
        float* d = s + r * 65 + c;
        d[0] = val.x; d[1] = val.y; d[2] = val.z; d[3] = val.w;
    }
}

// ---------------- mask scan: per-batch compaction index ----------------------
__global__ void scan_kernel(const int* __restrict__ mask) {
    int b = blockIdx.x;
    int t = threadIdx.x;              // 1024 threads, 9 tokens each
    int base = b * NN;
    int m[9], cnt = 0;
#pragma unroll
    for (int i = 0; i < 9; ++i) {
        m[i] = mask[base + t * 9 + i];
        cnt += m[i];
    }
    int lane = t & 31, wid = t >> 5;
    int v = cnt;
#pragma unroll
    for (int o = 1; o < 32; o <<= 1) {
        int n = __shfl_up_sync(0xffffffffu, v, o);
        if (lane >= o) v += n;
    }
    __shared__ int wsum[32];
    if (lane == 31) wsum[wid] = v;
    __syncthreads();
    if (wid == 0) {
        int x = wsum[lane];
#pragma unroll
        for (int o = 1; o < 32; o <<= 1) {
            int n = __shfl_up_sync(0xffffffffu, x, o);
            if (lane >= o) x += n;
        }
        wsum[lane] = x;
    }
    __syncthreads();
    int p = v - cnt + (wid > 0 ? wsum[wid - 1] : 0);
#pragma unroll
    for (int i = 0; i < 9; ++i) {
        if (m[i]) { g_cidx[base + p] = t * 9 + i; ++p; }
    }
    if (t == 1023) g_nv[b] = p;
}

// ---------------- LN1 + QKV fused (+ zero OUT rows for invalid tokens) ------
__global__ void qkvln_kernel(const float* __restrict__ x,
                             const int* __restrict__ mask,
                             float* __restrict__ out,
                             const float* __restrict__ g1, const float* __restrict__ b1,
                             const float* __restrict__ wq, const float* __restrict__ bq,
                             const float* __restrict__ wk, const float* __restrict__ bk,
                             const float* __restrict__ wv, const float* __restrict__ bv) {
    __shared__ float sA[64 * 65];    // x (channel-major), later weight tile
    __shared__ float sh[64 * 65];    // h (token-major)
    int tid = threadIdx.x;
    int token0 = blockIdx.x * 64;
    int bb = token0 / NN;
    int n0 = token0 - bb * NN;

    // zero final output for invalid tokens (valid ones written by tail_kernel)
    // coalesced: consecutive tid -> consecutive n
    for (int i = tid; i < 64 * CC; i += 256) {
        int tl = i & 63, c = i >> 6;
        if (!mask[token0 + tl])
            out[(size_t)bb * CC * NN + (size_t)c * NN + n0 + tl] = 0.0f;
    }

#pragma unroll
    for (int it = 0; it < 4; ++it) {
        int l = tid + it * 256;
        int c = l >> 4, t4 = (l & 15) * 4;
        float4 val = *(const float4*)(x + (size_t)bb * CC * NN + (size_t)c * NN + n0 + t4);
        float* d = sA + c * 65 + t4;
        d[0] = val.x; d[1] = val.y; d[2] = val.z; d[3] = val.w;
    }
    __syncthreads();

    {
        int w = tid >> 5, lane = tid & 31;
        float gg0 = g1[lane], gg1 = g1[lane + 32];
        float bb0 = b1[lane], bb1 = b1[lane + 32];
#pragma unroll
        for (int i = 0; i < 8; ++i) {
            int tok = w * 8 + i;
            float v0 = sA[lane * 65 + tok];
            float v1 = sA[(lane + 32) * 65 + tok];
            float s = v0 + v1, ss = v0 * v0 + v1 * v1;
#pragma unroll
            for (int o = 16; o; o >>= 1) {
                s  += __shfl_xor_sync(0xffffffffu, s,  o);
                ss += __shfl_xor_sync(0xffffffffu, ss, o);
            }
            float mu  = s * (1.0f / CC);
            float var = ss * (1.0f / CC) - mu * mu;
            float rs  = rsqrtf(var + 1e-5f);
            float h0 = (v0 - mu) * rs * gg0 + bb0;
            float h1 = (v1 - mu) * rs * gg1 + bb1;
            sh[tok * 65 + lane]      = h0;
            sh[tok * 65 + lane + 32] = h1;
            float* gp = g_h + (size_t)(token0 + tok) * CC;
            gp[lane]      = h0;
            gp[lane + 32] = h1;
        }
    }

    const float* ws[3] = {wq, wk, wv};
    const float* bs[3] = {bq, bk, bv};
    __nv_bfloat16* outs[3] = {g_qh, g_kh, g_vh};
    int ty = tid >> 4, tx = tid & 15;

    for (int m = 0; m < 3; ++m) {
        __syncthreads();
        load_tile64(ws[m], sA, tid);
        __syncthreads();
        float acc[4][4] = {};
        for (int kk = 0; kk < 64; ++kk) {
            float a[4], bv4[4];
#pragma unroll
            for (int i = 0; i < 4; ++i) a[i]   = sh[(ty * 4 + i) * 65 + kk];
#pragma unroll
            for (int j = 0; j < 4; ++j) bv4[j] = sA[(tx * 4 + j) * 65 + kk];
#pragma unroll
            for (int i = 0; i < 4; ++i)
#pragma unroll
                for (int j = 0; j < 4; ++j) acc[i][j] = fmaf(a[i], bv4[j], acc[i][j]);
        }
        float4 bias = ((const float4*)bs[m])[tx];
        float qs = (m == 0) ? SCALE : 1.0f;
#pragma unroll
        for (int i = 0; i < 4; ++i) {
            int r = token0 + ty * 4 + i;
            __nv_bfloat162* op = (__nv_bfloat162*)(outs[m] + (size_t)r * CC);
            op[tx * 2]     = __float22bfloat162_rn(
                make_float2((acc[i][0] + bias.x) * qs, (acc[i][1] + bias.y) * qs));
            op[tx * 2 + 1] = __float22bfloat162_rn(
                make_float2((acc[i][2] + bias.z) * qs, (acc[i][3] + bias.w) * qs));
        }
    }
}

// ---------------- Flash attention on COMPACTED tokens ------------------------
// BQ=64 queries/block; 16 warps = 4 row-slabs (wr) x 4 key-quarters (wc).
// K/V gathered via g_cidx inside cp.async. Tail padding masked by col<nv.
#define ATT_SMEM 74752
__global__ __launch_bounds__(512, 1) void attn2_kernel() {
    extern __shared__ __align__(128) char sm[];
    uint32_t sb = (uint32_t)__cvta_generic_to_shared(sm);
    const uint32_t K_OFF[2] = {8192u, 24576u};
    const uint32_t V_OFF[2] = {40960u, 57344u};
    const uint32_t LS = 73728u;

    int tid = threadIdx.x, lane = tid & 31, w = tid >> 5;
    int wr = w & 3, wc = w >> 2;
    int b = blockIdx.y, q0 = blockIdx.x * 64;
    int nv = g_nv[b];
    if (q0 >= nv) return;
    int ktiles = (nv + BK - 1) >> 7;
    const int* cidx = g_cidx + b * NN;

    {
        int row = tid >> 3, ch = tid & 7;
        int p = q0 + row;
        if (p >= nv) p = 0;
        int tok = cidx[p];
        uint4 v = *(const uint4*)(g_qh + ((size_t)b * NN + tok) * CC + ch * 8);
        *(uint4*)(sm + SWZ(row * 128 + ch * 16)) = v;
    }
    {
        int l = tid * 2;
        int row = l >> 3, ch = l & 7;
        int p = row;
        if (p >= nv) p = 0;
        int tok = cidx[p];
        const char* kz = (const char*)(g_kh + ((size_t)b * NN + tok) * CC);
        const char* vz = (const char*)(g_vh + ((size_t)b * NN + tok) * CC);
        uint32_t o0 = SWZ((uint32_t)(row * 128 + ch * 16));
        uint32_t o1 = SWZ((uint32_t)(row * 128 + ch * 16 + 16));
        cpa16(sb + K_OFF[0] + o0, kz + ch * 16);
        cpa16(sb + K_OFF[0] + o1, kz + ch * 16 + 16);
        cpa16(sb + V_OFF[0] + o0, vz + ch * 16);
        cpa16(sb + V_OFF[0] + o1, vz + ch * 16 + 16);
        cpa_commit();
    }
    __syncthreads();

    uint32_t qa[4][4];
    {
        int rowA = 16 * wr + (lane & 7) + ((lane >> 3) & 1) * 8;
        int cA   = ((lane >> 4) & 1) * 16;
#pragma unroll
        for (int ks = 0; ks < 4; ++ks) {
            uint32_t off = (uint32_t)(rowA * 128 + cA + ks * 32);
            ldsm_x4(qa[ks][0], qa[ks][1], qa[ks][2], qa[ks][3], sb + SWZ(off));
        }
    }

    float o[8][4];
#pragma unroll
    for (int t = 0; t < 8; ++t)
#pragma unroll
        for (int j = 0; j < 4; ++j) o[t][j] = 0.0f;
    uint64_t lq0 = 0, lq1 = 0;

    const uint64_t C1 = pk2(1.0f, 1.0f);
    const uint64_t C2 = pk2(0.5f, 0.5f);
    const uint64_t C3 = pk2(1.0f / 6.0f, 1.0f / 6.0f);
    const uint64_t C4 = pk2(1.0f / 24.0f, 1.0f / 24.0f);

    int r0 = 16 * wr + (lane >> 2), r1 = r0 + 8;
    int cq = (lane & 3) * 2;
    int rowF = (lane & 7) + ((lane >> 3) & 1) * 8;
    int cF   = ((lane >> 4) & 1) * 16;
    int kb   = 32 * wc;

    for (int kt = 0; kt < ktiles; ++kt) {
        int cur = kt & 1;
        cpa_wait<0>();
        __syncthreads();

        if (kt + 1 < ktiles) {
            int k1 = (kt + 1) * BK;
            int nxt = cur ^ 1;
            int l = tid * 2;
            int row = l >> 3, ch = l & 7;
            int p = k1 + row;
            if (p >= nv) p = 0;
            int tok = cidx[p];
            const char* kz = (const char*)(g_kh + ((size_t)b * NN + tok) * CC);
            const char* vz = (const char*)(g_vh + ((size_t)b * NN + tok) * CC);
            uint32_t o0 = SWZ((uint32_t)(row * 128 + ch * 16));
            uint32_t o1 = SWZ((uint32_t)(row * 128 + ch * 16 + 16));
            cpa16(sb + K_OFF[nxt] + o0, kz + ch * 16);
            cpa16(sb + K_OFF[nxt] + o1, kz + ch * 16 + 16);
            cpa16(sb + V_OFF[nxt] + o0, vz + ch * 16);
            cpa16(sb + V_OFF[nxt] + o1, vz + ch * 16 + 16);
            cpa_commit();
        }

        uint32_t kbK = sb + K_OFF[cur];
        uint32_t kbV = sb + V_OFF[cur];

        float s[4][4];
#pragma unroll
        for (int t = 0; t < 4; ++t)
#pragma unroll
            for (int j = 0; j < 4; ++j) s[t][j] = 0.0f;
#pragma unroll
        for (int ks = 0; ks < 4; ++ks) {
#pragma unroll
            for (int nt2 = 0; nt2 < 2; ++nt2) {
                int n0 = kb + 16 * nt2;
                uint32_t off = (uint32_t)((n0 + rowF) * 128 + cF + ks * 32);
                uint32_t f0, f1, f2, f3;
                ldsm_x4(f0, f1, f2, f3, kbK + SWZ(off));
                mma_bf16(s[2 * nt2],     qa[ks], f0, f2);
                mma_bf16(s[2 * nt2 + 1], qa[ks], f1, f3);
            }
        }

        int base_col = kt * BK + kb;
        uint32_t pb[4][2];
#pragma unroll
        for (int t = 0; t < 4; ++t) {
            int colb = base_col + 8 * t + cq;
            float mb0 = (colb < nv)     ? 1.0f : 0.0f;
            float mb1 = (colb + 1 < nv) ? 1.0f : 0.0f;
            uint64_t mp = pk2(mb0, mb1);
            uint64_t x0 = pk2(s[t][0], s[t][1]);
            uint64_t x1 = pk2(s[t][2], s[t][3]);
            uint64_t p0 = fma2(x0, C4, C3);
            p0 = fma2(p0, x0, C2);
            p0 = fma2(p0, x0, C1);
            p0 = fma2(p0, x0, C1);
            uint64_t p1 = fma2(x1, C4, C3);
            p1 = fma2(p1, x1, C2);
            p1 = fma2(p1, x1, C1);
            p1 = fma2(p1, x1, C1);
            p0 = mul2(p0, mp);
            p1 = mul2(p1, mp);
            lq0 = add2(lq0, p0);
            lq1 = add2(lq1, p1);
            float a0, a1, b0v, b1v;
            upk2(a0, a1, p0);
            upk2(b0v, b1v, p1);
            pb[t][0] = cvtbf2(a0, a1);
            pb[t][1] = cvtbf2(b0v, b1v);
        }

#pragma unroll
        for (int ks2 = 0; ks2 < 2; ++ks2) {
            uint32_t pa[4];
            pa[0] = pb[2 * ks2][0];
            pa[1] = pb[2 * ks2][1];
            pa[2] = pb[2 * ks2 + 1][0];
            pa[3] = pb[2 * ks2 + 1][1];
            int kr = kb + 16 * ks2;
#pragma unroll
            for (int nt2 = 0; nt2 < 4; ++nt2) {
                uint32_t off = (uint32_t)((kr + rowF) * 128 + nt2 * 32 + cF);
                uint32_t v0, v1, v2, v3;
                ldsm_x4_t(v0, v1, v2, v3, kbV + SWZ(off));
                mma_bf16(o[2 * nt2],     pa, v0, v1);
                mma_bf16(o[2 * nt2 + 1], pa, v2, v3);
            }
        }
    }

    float la, lb2, lp0, lp1;
    upk2(la, lb2, lq0); lp0 = la + lb2;
    upk2(la, lb2, lq1); lp1 = la + lb2;
    lp0 += __shfl_xor_sync(0xffffffffu, lp0, 1);
    lp0 += __shfl_xor_sync(0xffffffffu, lp0, 2);
    lp1 += __shfl_xor_sync(0xffffffffu, lp1, 1);
    lp1 += __shfl_xor_sync(0xffffffffu, lp1, 2);
    __syncthreads();
    float* lsum = (float*)(sm + LS);            // [4][64]
    if ((lane & 3) == 0) { lsum[wc * 64 + r0] = lp0; lsum[wc * 64 + r1] = lp1; }
    if (wc > 0) {
        float* sO = (float*)(sm + 8192 + (wc - 1) * 17152);
#pragma unroll
        for (int t = 0; t < 8; ++t) {
            int col = 8 * t + cq;
            sO[r0 * 66 + col]     = o[t][0];
            sO[r0 * 66 + col + 1] = o[t][1];
            sO[r1 * 66 + col]     = o[t][2];
            sO[r1 * 66 + col + 1] = o[t][3];
        }
    }
    __syncthreads();
    if (wc == 0) {
        float* s1 = (float*)(sm + 8192);
        float* s2 = (float*)(sm + 8192 + 17152);
        float* s3 = (float*)(sm + 8192 + 34304);
        float lt0 = lsum[r0] + lsum[64 + r0] + lsum[128 + r0] + lsum[192 + r0];
        float lt1 = lsum[r1] + lsum[64 + r1] + lsum[128 + r1] + lsum[192 + r1];
        float inv0 = 1.0f / lt0;
        float inv1 = 1.0f / lt1;
        int p0r = q0 + r0, p1r = q0 + r1;
        bool w0 = p0r < nv, w1 = p1r < nv;
        int tok0 = w0 ? cidx[p0r] : 0;
        int tok1 = w1 ? cidx[p1r] : 0;
        float* d0 = g_att + ((size_t)b * NN + tok0) * CC;
        float* d1 = g_att + ((size_t)b * NN + tok1) * CC;
#pragma unroll
        for (int t = 0; t < 8; ++t) {
            int col = 8 * t + cq;
            if (w0)
                *(float2*)(d0 + col) = make_float2(
                    (o[t][0] + s1[r0 * 66 + col] + s2[r0 * 66 + col] + s3[r0 * 66 + col]) * inv0,
                    (o[t][1] + s1[r0 * 66 + col + 1] + s2[r0 * 66 + col + 1] + s3[r0 * 66 + col + 1]) * inv0);
            if (w1)
                *(float2*)(d1 + col) = make_float2(
                    (o[t][2] + s1[r1 * 66 + col] + s2[r1 * 66 + col] + s3[r1 * 66 + col]) * inv1,
                    (o[t][3] + s1[r1 * 66 + col + 1] + s2[r1 * 66 + col + 1] + s3[r1 * 66 + col + 1]) * inv1);
        }
    }
}

// ---------------- Fused tail on COMPACTED tokens ------------------------------
// Gathers 64 valid rows via cidx, computes oproj+LN2+FFN, scatters to out.
#define TAIL_SMEM (4 * 64 * 65 * 4 + 256)
__global__ void tail_kernel(const float* __restrict__ wo, const float* __restrict__ bo,
                            const float* __restrict__ g2, const float* __restrict__ b2,
                            const float* __restrict__ w1, const float* __restrict__ bf1,
                            const float* __restrict__ w2, const float* __restrict__ bf2,
                            float* __restrict__ out) {
    extern __shared__ float smf[];
    float* B0 = smf;
    float* B1 = smf + 4160;
    float* B2 = smf + 8320;
    float* B3 = smf + 12480;
    int*   rows = (int*)(smf + 16640);   // [64] gathered token ids (b*NN + tok)
    int tid = threadIdx.x;
    int b = blockIdx.y;
    int q0 = blockIdx.x * 64;
    int nv = g_nv[b];
    if (q0 >= nv) return;
    int ty = tid >> 4, tx = tid & 15;

    if (tid < 64) {
        int p = q0 + tid;
        if (p >= nv) p = nv - 1;       // clamp: duplicate valid row, discarded
        rows[tid] = b * NN + g_cidx[b * NN + p];
    }
    __syncthreads();

    load_tile64_g(g_att, rows, B0, tid);
    load_tile64(wo, B1, tid);
    __syncthreads();
    {
        float acc[4][4] = {};
        for (int kk = 0; kk < 64; ++kk) {
            float a[4], bv4[4];
#pragma unroll
            for (int i = 0; i < 4; ++i) a[i]   = B0[(ty * 4 + i) * 65 + kk];
#pragma unroll
            for (int j = 0; j < 4; ++j) bv4[j] = B1[(tx * 4 + j) * 65 + kk];
#pragma unroll
            for (int i = 0; i < 4; ++i)
#pragma unroll
                for (int j = 0; j < 4; ++j) acc[i][j] = fmaf(a[i], bv4[j], acc[i][j]);
        }
        float4 bias = ((const float4*)bo)[tx];
#pragma unroll
        for (int i = 0; i < 4; ++i) {
            float4 hv = ((const float4*)(g_h + (size_t)rows[ty * 4 + i] * CC))[tx];
            float* d = B2 + (ty * 4 + i) * 65 + tx * 4;
            d[0] = acc[i][0] + bias.x + hv.x;
            d[1] = acc[i][1] + bias.y + hv.y;
            d[2] = acc[i][2] + bias.z + hv.z;
            d[3] = acc[i][3] + bias.w + hv.w;
        }
    }
    __syncthreads();

    {
        int w = tid >> 5, lane = tid & 31;
        float gg0 = g2[lane], gg1 = g2[lane + 32];
        float bb0 = b2[lane], bb1 = b2[lane + 32];
#pragma unroll
        for (int i = 0; i < 8; ++i) {
            int r = w * 8 + i;
            float v0 = B2[r * 65 + lane];
            float v1 = B2[r * 65 + lane + 32];
            float s = v0 + v1, ss = v0 * v0 + v1 * v1;
#pragma unroll
            for (int off = 16; off; off >>= 1) {
                s  += __shfl_xor_sync(0xffffffffu, s,  off);
                ss += __shfl_xor_sync(0xffffffffu, ss, off);
            }
            float mu  = s * (1.0f / CC);
            float var = ss * (1.0f / CC) - mu * mu;
            float rs  = rsqrtf(var + 1e-5f);
            B3[r * 65 + lane]      = (v0 - mu) * rs * gg0 + bb0;
            B3[r * 65 + lane + 32] = (v1 - mu) * rs * gg1 + bb1;
        }
    }
    __syncthreads();

    float acc2[4][4] = {};
    for (int chunk = 0; chunk < 4; ++chunk) {
        load_tile64(w1 + (size_t)chunk * 64 * CC, B1, tid);
        __syncthreads();
        {
            float acc[4][4] = {};
            for (int kk = 0; kk < 64; ++kk) {
                float a[4], bv4[4];
#pragma unroll
                for (int i = 0; i < 4; ++i) a[i]   = B3[(ty * 4 + i) * 65 + kk];
#pragma unroll
                for (int j = 0; j < 4; ++j) bv4[j] = B1[(tx * 4 + j) * 65 + kk];
#pragma unroll
                for (int i = 0; i < 4; ++i)
#pragma unroll
                    for (int j = 0; j < 4; ++j) acc[i][j] = fmaf(a[i], bv4[j], acc[i][j]);
            }
            float4 bias = ((const float4*)(bf1 + chunk * 64))[tx];
            float ba[4] = {bias.x, bias.y, bias.z, bias.w};
#pragma unroll
            for (int i = 0; i < 4; ++i) {
                float* d = B0 + (ty * 4 + i) * 65 + tx * 4;
#pragma unroll
                for (int j = 0; j < 4; ++j) {
                    float v = acc[i][j] + ba[j];
                    d[j] = 0.5f * v * (1.0f + erff(v * 0.70710678118654752f));
                }
            }
        }
        __syncthreads();
#pragma unroll
        for (int it = 0; it < 4; ++it) {
            int l = tid + it * 256;
            int r = l >> 4, c4 = (l & 15) * 4;
            float4 val = *(const float4*)(w2 + (size_t)r * HID + chunk * 64 + c4);
            float* d = B2 + r * 65 + c4;
            d[0] = val.x; d[1] = val.y; d[2] = val.z; d[3] = val.w;
        }
        __syncthreads();
        for (int kk = 0; kk < 64; ++kk) {
            float a[4], bv4[4];
#pragma unroll
            for (int i = 0; i < 4; ++i) a[i]   = B0[(ty * 4 + i) * 65 + kk];
#pragma unroll
            for (int j = 0; j < 4; ++j) bv4[j] = B2[(tx * 4 + j) * 65 + kk];
#pragma unroll
            for (int i = 0; i < 4; ++i)
#pragma unroll
                for (int j = 0; j < 4; ++j) acc2[i][j] = fmaf(a[i], bv4[j], acc2[i][j]);
        }
        __syncthreads();
    }

    float4 bias = ((const float4*)bf2)[tx];
    float ba[4] = {bias.x, bias.y, bias.z, bias.w};
#pragma unroll
    for (int i = 0; i < 4; ++i) {
        int p = q0 + ty * 4 + i;
        if (p >= nv) continue;          // padding rows: discard
        int n = rows[ty * 4 + i] - b * NN;
#pragma unroll
        for (int j = 0; j < 4; ++j) {
            int c = tx * 4 + j;
            out[(size_t)b * CC * NN + (size_t)c * NN + n] =
                acc2[i][j] + ba[j] + B3[(ty * 4 + i) * 65 + c];
        }
    }
}

// ---------------- launch ----------------------------------------------------
extern "C" void kernel_launch(void* const* d_in, const int* in_sizes, int n_in,
                              void* d_out, int out_size) {
    const float* x    = (const float*)d_in[0];
    const int*   mask = (const int*)  d_in[1];
    const float* wq   = (const float*)d_in[2];
    const float* bq   = (const float*)d_in[3];
    const float* wk   = (const float*)d_in[4];
    const float* bk   = (const float*)d_in[5];
    const float* wv   = (const float*)d_in[6];
    const float* bv   = (const float*)d_in[7];
    const float* wo   = (const float*)d_in[8];
    const float* bo   = (const float*)d_in[9];
    const float* g1   = (const float*)d_in[10];
    const float* b1   = (const float*)d_in[11];
    const float* g2   = (const float*)d_in[12];
    const float* b2   = (const float*)d_in[13];
    const float* w1   = (const float*)d_in[14];
    const float* bf1  = (const float*)d_in[15];
    const float* w2   = (const float*)d_in[16];
    const float* bf2  = (const float*)d_in[17];
    float* out = (float*)d_out;

    cudaFuncSetAttribute(attn2_kernel, cudaFuncAttributeMaxDynamicSharedMemorySize,
                         ATT_SMEM);
    cudaFuncSetAttribute(tail_kernel, cudaFuncAttributeMaxDynamicSharedMemorySize,
                         TAIL_SMEM);

    scan_kernel<<<BBATCH, 1024>>>(mask);
    qkvln_kernel<<<BNTOK / 64, 256>>>(x, mask, out, g1, b1, wq, bq, wk, bk, wv, bv);
    attn2_kernel<<<dim3(NN / 64, BBATCH), 512, ATT_SMEM>>>();
    tail_kernel<<<dim3(NN / 64, BBATCH), 256, TAIL_SMEM>>>(wo, bo, g2, b2, w1, bf1,
                                                           w2, bf2, out);
}